// round 1
// baseline (speedup 1.0000x reference)
#include <cuda_runtime.h>

// IF spiking neuron forward (non-align, T>0):
//   xs = x.reshape(T, B, 1024, 3072)
//   mem0 = dtmem * thresh
//   for t: mem += x_t; spike = (mem >= thresh) ? thresh : 0; mem -= spike
// Inputs: d_in[0] = x (T*B*1024*3072 f32), d_in[1] = thresh2 (1024*3072),
//         d_in[2] = dtmem (1024*3072). Output: spikes, same shape as x.

#define T_STEPS 4

__global__ __launch_bounds__(256) void if_fwd_kernel(
    const float4* __restrict__ x,      // [T, n_per_t] in vec4 units
    const float4* __restrict__ thresh, // [feat_v] vec4
    const float4* __restrict__ dtmem,  // [feat_v] vec4
    float4* __restrict__ out,          // [T, n_per_t]
    int n_per_t,                       // B*1024*3072/4
    int feat_v)                        // 1024*3072/4
{
    int i = blockIdx.x * blockDim.x + threadIdx.x;
    if (i >= n_per_t) return;

    int f = i % feat_v;  // feature index within (1024,3072), batch-broadcast

    float4 th = thresh[f];
    float4 dm = dtmem[f];

    float4 mem;
    mem.x = dm.x * th.x;
    mem.y = dm.y * th.y;
    mem.z = dm.z * th.z;
    mem.w = dm.w * th.w;

#pragma unroll
    for (int t = 0; t < T_STEPS; t++) {
        float4 xv = __ldg(&x[(long long)t * n_per_t + i]);
        float4 sp;

        mem.x += xv.x;
        sp.x = (mem.x >= th.x) ? th.x : 0.0f;
        mem.x -= sp.x;

        mem.y += xv.y;
        sp.y = (mem.y >= th.y) ? th.y : 0.0f;
        mem.y -= sp.y;

        mem.z += xv.z;
        sp.z = (mem.z >= th.z) ? th.z : 0.0f;
        mem.z -= sp.z;

        mem.w += xv.w;
        sp.w = (mem.w >= th.w) ? th.w : 0.0f;
        mem.w -= sp.w;

        out[(long long)t * n_per_t + i] = sp;
    }
}

extern "C" void kernel_launch(void* const* d_in, const int* in_sizes, int n_in,
                              void* d_out, int out_size) {
    const float* x      = (const float*)d_in[0];
    const float* thresh = (const float*)d_in[1];
    const float* dtmem  = (const float*)d_in[2];
    float* out          = (float*)d_out;

    int total   = in_sizes[0];          // T*B*1024*3072
    int feat_n  = in_sizes[1];          // 1024*3072
    int n_per_t = total / T_STEPS;      // B*1024*3072 (elements)

    int n_per_t_v = n_per_t / 4;        // vec4 units
    int feat_v    = feat_n / 4;

    int threads = 256;
    int blocks = (n_per_t_v + threads - 1) / threads;

    if_fwd_kernel<<<blocks, threads>>>(
        (const float4*)x, (const float4*)thresh, (const float4*)dtmem,
        (float4*)out, n_per_t_v, feat_v);
}

// round 2
// speedup vs baseline: 1.1600x; 1.1600x over previous
#include <cuda_runtime.h>

// IF spiking neuron forward:
//   mem0 = dtmem * thresh
//   for t: mem += x_t; spike = (mem >= thresh) ? thresh : 0; mem -= spike
//
// Mapping: one thread per feature-vec4; batch loop (B) inside the thread so
// thresh/dtmem are loaded exactly once per thread. x/out accessed with
// streaming hints (no reuse) to preserve L2 for params.

#define T_STEPS 4

__global__ __launch_bounds__(256) void if_fwd_kernel(
    const float4* __restrict__ x,      // [T, B, feat_v]
    const float4* __restrict__ thresh, // [feat_v]
    const float4* __restrict__ dtmem,  // [feat_v]
    float4* __restrict__ out,          // [T, B, feat_v]
    int feat_v,                        // 1024*3072/4
    int n_per_t_v,                     // B*feat_v (t-stride in vec4)
    int B)
{
    int f = blockIdx.x * blockDim.x + threadIdx.x;
    if (f >= feat_v) return;

    float4 th = thresh[f];
    float4 dm = dtmem[f];

    float4 mem0;
    mem0.x = dm.x * th.x;
    mem0.y = dm.y * th.y;
    mem0.z = dm.z * th.z;
    mem0.w = dm.w * th.w;

    for (int b = 0; b < B; b++) {
        long long base = (long long)b * feat_v + f;

        // Front-batch the 4 time-step loads (independent -> MLP=4).
        float4 xv0 = __ldcs(&x[base]);
        float4 xv1 = __ldcs(&x[base + (long long)n_per_t_v]);
        float4 xv2 = __ldcs(&x[base + 2LL * n_per_t_v]);
        float4 xv3 = __ldcs(&x[base + 3LL * n_per_t_v]);

        float4 mem = mem0;
        float4 sp;

#define STEP(xv, tidx)                                            \
        mem.x += xv.x; sp.x = (mem.x >= th.x) ? th.x : 0.0f; mem.x -= sp.x; \
        mem.y += xv.y; sp.y = (mem.y >= th.y) ? th.y : 0.0f; mem.y -= sp.y; \
        mem.z += xv.z; sp.z = (mem.z >= th.z) ? th.z : 0.0f; mem.z -= sp.z; \
        mem.w += xv.w; sp.w = (mem.w >= th.w) ? th.w : 0.0f; mem.w -= sp.w; \
        __stcs(&out[base + (long long)(tidx) * n_per_t_v], sp);

        STEP(xv0, 0)
        STEP(xv1, 1)
        STEP(xv2, 2)
        STEP(xv3, 3)
#undef STEP
    }
}

extern "C" void kernel_launch(void* const* d_in, const int* in_sizes, int n_in,
                              void* d_out, int out_size) {
    const float* x      = (const float*)d_in[0];
    const float* thresh = (const float*)d_in[1];
    const float* dtmem  = (const float*)d_in[2];
    float* out          = (float*)d_out;

    int total  = in_sizes[0];           // T*B*1024*3072
    int feat_n = in_sizes[1];           // 1024*3072
    int B      = total / (T_STEPS * feat_n);

    int feat_v    = feat_n / 4;
    int n_per_t_v = B * feat_v;

    int threads = 256;
    int blocks = (feat_v + threads - 1) / threads;

    if_fwd_kernel<<<blocks, threads>>>(
        (const float4*)x, (const float4*)thresh, (const float4*)dtmem,
        (float4*)out, feat_v, n_per_t_v, B);
}

// round 3
// speedup vs baseline: 1.1721x; 1.0104x over previous
#include <cuda_runtime.h>

// IF spiking neuron forward:
//   mem0 = dtmem * thresh
//   for t: mem += x_t; spike = (mem >= thresh) ? thresh : 0; mem -= spike
//
// Mapping: grid.y = feature chunks, grid.x = 4-way batch split (fast launch
// dim, so blocks sharing params launch adjacently -> L2-served param reads).
// Each thread: 1 feature-vec4, B/4 = 2 batch iterations, T loop in registers.

#define T_STEPS 4
#define BSPLIT  4

__global__ __launch_bounds__(256) void if_fwd_kernel(
    const float4* __restrict__ x,      // [T, B, feat_v]
    const float4* __restrict__ thresh, // [feat_v]
    const float4* __restrict__ dtmem,  // [feat_v]
    float4* __restrict__ out,          // [T, B, feat_v]
    int feat_v,                        // 1024*3072/4
    int n_per_t_v,                     // B*feat_v (t-stride in vec4)
    int b_per_blk)                     // B / BSPLIT
{
    int f = blockIdx.y * blockDim.x + threadIdx.x;
    if (f >= feat_v) return;

    int b0 = blockIdx.x * b_per_blk;

    float4 th = thresh[f];
    float4 dm = dtmem[f];

    float4 mem0;
    mem0.x = dm.x * th.x;
    mem0.y = dm.y * th.y;
    mem0.z = dm.z * th.z;
    mem0.w = dm.w * th.w;

#pragma unroll
    for (int bi = 0; bi < 2; bi++) {
        int b = b0 + bi;
        long long base = (long long)b * feat_v + f;

        // Front-batch the 4 time-step loads (independent -> MLP=4).
        float4 xv0 = __ldcs(&x[base]);
        float4 xv1 = __ldcs(&x[base + (long long)n_per_t_v]);
        float4 xv2 = __ldcs(&x[base + 2LL * n_per_t_v]);
        float4 xv3 = __ldcs(&x[base + 3LL * n_per_t_v]);

        float4 mem = mem0;
        float4 sp;

#define STEP(xv, tidx)                                            \
        mem.x += xv.x; sp.x = (mem.x >= th.x) ? th.x : 0.0f; mem.x -= sp.x; \
        mem.y += xv.y; sp.y = (mem.y >= th.y) ? th.y : 0.0f; mem.y -= sp.y; \
        mem.z += xv.z; sp.z = (mem.z >= th.z) ? th.z : 0.0f; mem.z -= sp.z; \
        mem.w += xv.w; sp.w = (mem.w >= th.w) ? th.w : 0.0f; mem.w -= sp.w; \
        __stcs(&out[base + (long long)(tidx) * n_per_t_v], sp);

        STEP(xv0, 0)
        STEP(xv1, 1)
        STEP(xv2, 2)
        STEP(xv3, 3)
#undef STEP
    }
}

extern "C" void kernel_launch(void* const* d_in, const int* in_sizes, int n_in,
                              void* d_out, int out_size) {
    const float* x      = (const float*)d_in[0];
    const float* thresh = (const float*)d_in[1];
    const float* dtmem  = (const float*)d_in[2];
    float* out          = (float*)d_out;

    int total  = in_sizes[0];           // T*B*1024*3072
    int feat_n = in_sizes[1];           // 1024*3072
    int B      = total / (T_STEPS * feat_n);

    int feat_v    = feat_n / 4;
    int n_per_t_v = B * feat_v;
    int b_per_blk = B / BSPLIT;         // 2

    int threads = 256;
    dim3 grid(BSPLIT, (feat_v + threads - 1) / threads);

    if_fwd_kernel<<<grid, threads>>>(
        (const float4*)x, (const float4*)thresh, (const float4*)dtmem,
        (float4*)out, feat_v, n_per_t_v, b_per_blk);
}

// round 4
// speedup vs baseline: 1.1754x; 1.0028x over previous
#include <cuda_runtime.h>

// IF spiking neuron forward:
//   mem0 = dtmem * thresh
//   for t: mem += x_t; spike = (mem >= thresh) ? thresh : 0; mem -= spike
//
// Mapping: one thread per (batch, feature-vec4) site; T loop in registers.
// grid.x = B (fast launch dim -> the B blocks sharing a feature chunk's
// params launch adjacently, so thresh/dtmem reads after the first are
// L2-served). grid.y = feature chunks. Streaming hints on x/out keep the
// 800MB stream from evicting the 25MB of params out of L2.

#define T_STEPS 4

__global__ __launch_bounds__(256, 7) void if_fwd_kernel(
    const float4* __restrict__ x,      // [T, B, feat_v]
    const float4* __restrict__ thresh, // [feat_v]
    const float4* __restrict__ dtmem,  // [feat_v]
    float4* __restrict__ out,          // [T, B, feat_v]
    int feat_v,                        // 1024*3072/4
    int n_per_t_v)                     // B*feat_v (t-stride in vec4)
{
    int f = blockIdx.y * blockDim.x + threadIdx.x;
    if (f >= feat_v) return;

    int b = blockIdx.x;
    long long base = (long long)b * feat_v + f;

    // Front-batch the 4 time-step loads (independent -> MLP=4).
    float4 xv0 = __ldcs(&x[base]);
    float4 xv1 = __ldcs(&x[base + (long long)n_per_t_v]);
    float4 xv2 = __ldcs(&x[base + 2LL * n_per_t_v]);
    float4 xv3 = __ldcs(&x[base + 3LL * n_per_t_v]);

    float4 th = thresh[f];
    float4 dm = dtmem[f];

    float4 mem;
    mem.x = dm.x * th.x;
    mem.y = dm.y * th.y;
    mem.z = dm.z * th.z;
    mem.w = dm.w * th.w;

    float4 sp;

#define STEP(xv, tidx)                                                      \
    mem.x += xv.x; sp.x = (mem.x >= th.x) ? th.x : 0.0f; mem.x -= sp.x;     \
    mem.y += xv.y; sp.y = (mem.y >= th.y) ? th.y : 0.0f; mem.y -= sp.y;     \
    mem.z += xv.z; sp.z = (mem.z >= th.z) ? th.z : 0.0f; mem.z -= sp.z;     \
    mem.w += xv.w; sp.w = (mem.w >= th.w) ? th.w : 0.0f; mem.w -= sp.w;     \
    __stcs(&out[base + (long long)(tidx) * n_per_t_v], sp);

    STEP(xv0, 0)
    STEP(xv1, 1)
    STEP(xv2, 2)
    STEP(xv3, 3)
#undef STEP
}

extern "C" void kernel_launch(void* const* d_in, const int* in_sizes, int n_in,
                              void* d_out, int out_size) {
    const float* x      = (const float*)d_in[0];
    const float* thresh = (const float*)d_in[1];
    const float* dtmem  = (const float*)d_in[2];
    float* out          = (float*)d_out;

    int total  = in_sizes[0];           // T*B*1024*3072
    int feat_n = in_sizes[1];           // 1024*3072
    int B      = total / (T_STEPS * feat_n);

    int feat_v    = feat_n / 4;
    int n_per_t_v = B * feat_v;

    int threads = 256;
    dim3 grid(B, (feat_v + threads - 1) / threads);

    if_fwd_kernel<<<grid, threads>>>(
        (const float4*)x, (const float4*)thresh, (const float4*)dtmem,
        (float4*)out, feat_v, n_per_t_v);
}

// round 5
// speedup vs baseline: 1.1882x; 1.0108x over previous
#include <cuda_runtime.h>

// IF spiking neuron forward:
//   mem0 = dtmem * thresh
//   for t: mem += x_t; spike = (mem >= thresh) ? thresh : 0; mem -= spike
//
// Mapping: one thread per (batch, feature-vec4) site; T loop in registers.
// grid.x = B (fast launch dim -> blocks sharing a feature chunk's params
// launch adjacently, so thresh/dtmem reads after the first are L2-served).
// Default cache policy everywhere: R0-R4 A/B showed .cs hints cost ~6% of
// DRAM bandwidth on sm_103a (86.9% -> ~81%) with no traffic benefit.

#define T_STEPS 4

__global__ __launch_bounds__(256, 7) void if_fwd_kernel(
    const float4* __restrict__ x,      // [T, B, feat_v]
    const float4* __restrict__ thresh, // [feat_v]
    const float4* __restrict__ dtmem,  // [feat_v]
    float4* __restrict__ out,          // [T, B, feat_v]
    int feat_v,                        // 1024*3072/4
    int n_per_t_v)                     // B*feat_v (t-stride in vec4)
{
    int f = blockIdx.y * blockDim.x + threadIdx.x;
    if (f >= feat_v) return;

    int b = blockIdx.x;
    long long base = (long long)b * feat_v + f;

    // Front-batch the 4 time-step loads (independent -> MLP=4).
    float4 xv0 = __ldg(&x[base]);
    float4 xv1 = __ldg(&x[base + (long long)n_per_t_v]);
    float4 xv2 = __ldg(&x[base + 2LL * n_per_t_v]);
    float4 xv3 = __ldg(&x[base + 3LL * n_per_t_v]);

    float4 th = __ldg(&thresh[f]);
    float4 dm = __ldg(&dtmem[f]);

    float4 mem;
    mem.x = dm.x * th.x;
    mem.y = dm.y * th.y;
    mem.z = dm.z * th.z;
    mem.w = dm.w * th.w;

    float4 sp;

#define STEP(xv, tidx)                                                      \
    mem.x += xv.x; sp.x = (mem.x >= th.x) ? th.x : 0.0f; mem.x -= sp.x;     \
    mem.y += xv.y; sp.y = (mem.y >= th.y) ? th.y : 0.0f; mem.y -= sp.y;     \
    mem.z += xv.z; sp.z = (mem.z >= th.z) ? th.z : 0.0f; mem.z -= sp.z;     \
    mem.w += xv.w; sp.w = (mem.w >= th.w) ? th.w : 0.0f; mem.w -= sp.w;     \
    out[base + (long long)(tidx) * n_per_t_v] = sp;

    STEP(xv0, 0)
    STEP(xv1, 1)
    STEP(xv2, 2)
    STEP(xv3, 3)
#undef STEP
}

extern "C" void kernel_launch(void* const* d_in, const int* in_sizes, int n_in,
                              void* d_out, int out_size) {
    const float* x      = (const float*)d_in[0];
    const float* thresh = (const float*)d_in[1];
    const float* dtmem  = (const float*)d_in[2];
    float* out          = (float*)d_out;

    int total  = in_sizes[0];           // T*B*1024*3072
    int feat_n = in_sizes[1];           // 1024*3072
    int B      = total / (T_STEPS * feat_n);

    int feat_v    = feat_n / 4;
    int n_per_t_v = B * feat_v;

    int threads = 256;
    dim3 grid(B, (feat_v + threads - 1) / threads);

    if_fwd_kernel<<<grid, threads>>>(
        (const float4*)x, (const float4*)thresh, (const float4*)dtmem,
        (float4*)out, feat_v, n_per_t_v);
}